// round 1
// baseline (speedup 1.0000x reference)
#include <cuda_runtime.h>

// StructuralLoss: predictions (64, 8192, 60) fp32.
// For each of 64*8192 rows, 3 key blocks of 20 floats:
//   bid_l = v[2l] (l=0..4), ask_l = v[10+2l]
//   viol = sum_l max(ask_l - ask_{l+1},0) + sum_l max(bid_{l+1}-bid_l,0)
//        + max(bid0 - ask0, 0)
// output scalar = (1/64) * sum over all (row, key) units.

#define NBLOCKS 1184
#define NTHREADS 256

__device__ float g_partials[NBLOCKS];

__global__ __launch_bounds__(NTHREADS) void viol_kernel(
    const float* __restrict__ pred, int n_units)
{
    float acc = 0.0f;
    int stride = gridDim.x * blockDim.x;
    for (int u = blockIdx.x * blockDim.x + threadIdx.x; u < n_units; u += stride) {
        const float4* p = reinterpret_cast<const float4*>(pred + (long long)u * 20);
        float4 a = p[0];
        float4 b = p[1];
        float4 c = p[2];
        float4 d = p[3];
        float4 e = p[4];
        // v0..v19: a.x a.y a.z a.w | b.x .. | c.x .. | d.x .. | e.x e.y e.z e.w
        float bid0 = a.x, bid1 = a.z, bid2 = b.x, bid3 = b.z, bid4 = c.x;
        float ask0 = c.z, ask1 = d.x, ask2 = d.z, ask3 = e.x, ask4 = e.z;

        acc += fmaxf(ask0 - ask1, 0.0f);
        acc += fmaxf(ask1 - ask2, 0.0f);
        acc += fmaxf(ask2 - ask3, 0.0f);
        acc += fmaxf(ask3 - ask4, 0.0f);
        acc += fmaxf(bid1 - bid0, 0.0f);
        acc += fmaxf(bid2 - bid1, 0.0f);
        acc += fmaxf(bid3 - bid2, 0.0f);
        acc += fmaxf(bid4 - bid3, 0.0f);
        acc += fmaxf(bid0 - ask0, 0.0f);
    }

    // Deterministic block reduction: warp shuffle + shared
    __shared__ float s[NTHREADS / 32];
    #pragma unroll
    for (int o = 16; o > 0; o >>= 1)
        acc += __shfl_down_sync(0xffffffffu, acc, o);
    if ((threadIdx.x & 31) == 0) s[threadIdx.x >> 5] = acc;
    __syncthreads();
    if (threadIdx.x < 32) {
        float v = (threadIdx.x < NTHREADS / 32) ? s[threadIdx.x] : 0.0f;
        #pragma unroll
        for (int o = 16; o > 0; o >>= 1)
            v += __shfl_down_sync(0xffffffffu, v, o);
        if (threadIdx.x == 0) g_partials[blockIdx.x] = v;
    }
}

__global__ __launch_bounds__(256) void final_reduce(float* out)
{
    __shared__ float s[8];
    float acc = 0.0f;
    for (int i = threadIdx.x; i < NBLOCKS; i += blockDim.x)
        acc += g_partials[i];
    #pragma unroll
    for (int o = 16; o > 0; o >>= 1)
        acc += __shfl_down_sync(0xffffffffu, acc, o);
    if ((threadIdx.x & 31) == 0) s[threadIdx.x >> 5] = acc;
    __syncthreads();
    if (threadIdx.x == 0) {
        float t = 0.0f;
        #pragma unroll
        for (int i = 0; i < 8; i++) t += s[i];
        out[0] = t * (1.0f / 64.0f);
    }
}

extern "C" void kernel_launch(void* const* d_in, const int* in_sizes, int n_in,
                              void* d_out, int out_size)
{
    const float* pred = (const float*)d_in[0];
    float* out = (float*)d_out;
    int n_units = in_sizes[0] / 20;  // 64*8192*60 / 20 = 1,572,864

    viol_kernel<<<NBLOCKS, NTHREADS>>>(pred, n_units);
    final_reduce<<<1, 256>>>(out);
}